// round 14
// baseline (speedup 1.0000x reference)
#include <cuda_runtime.h>
#include <cuda_fp16.h>
#include <cstdint>

// ---------------- problem constants ----------------
#define NEXP 64
#define DIM  2048
#define HID  1024
#define TOK  16384
#define TPE  256

// scratch: fp16 SwiGLU intermediate + fp16 pre-converted X
__device__ __half g_h[(size_t)TOK * HID];
__device__ __half g_x[(size_t)TOK * DIM];

// ---------------- helpers ----------------
__device__ __forceinline__ uint32_t smem_u32(const void* p) {
    uint32_t a;
    asm("{ .reg .u64 t; cvta.to.shared.u64 t, %1; cvt.u32.u64 %0, t; }" : "=r"(a) : "l"(p));
    return a;
}
__device__ __forceinline__ uint32_t pkh2(float lo, float hi) {
    uint32_t r;
    asm("cvt.rn.f16x2.f32 %0, %1, %2;" : "=r"(r) : "f"(hi), "f"(lo));
    return r;
}

#define SWZ(x) ((x) ^ (((x) >> 3) & 0x70))

__device__ __forceinline__ void cp16(uint32_t dst, const void* src) {
    asm volatile("cp.async.cg.shared.global [%0], [%1], 16;" :: "r"(dst), "l"(src));
}
#define CP_COMMIT() asm volatile("cp.async.commit_group;" ::: "memory")
#define CP_WAIT1()  asm volatile("cp.async.wait_group 1;" ::: "memory")

__device__ __forceinline__ void ldsm4(uint32_t* f, uint32_t addr) {
    asm volatile("ldmatrix.sync.aligned.m8n8.x4.shared.b16 {%0,%1,%2,%3}, [%4];"
                 : "=r"(f[0]), "=r"(f[1]), "=r"(f[2]), "=r"(f[3]) : "r"(addr));
}

__device__ __forceinline__ void mma16(float* d, const uint32_t* a, uint32_t b0, uint32_t b1) {
    asm volatile("mma.sync.aligned.m16n8k16.row.col.f32.f16.f16.f32 "
                 "{%0,%1,%2,%3},{%4,%5,%6,%7},{%8,%9},{%0,%1,%2,%3};"
                 : "+f"(d[0]), "+f"(d[1]), "+f"(d[2]), "+f"(d[3])
                 : "r"(a[0]), "r"(a[1]), "r"(a[2]), "r"(a[3]), "r"(b0), "r"(b1));
}

__device__ __forceinline__ float silu(float v) {
    return v / (1.0f + __expf(-v));
}

// ---------------- smem layout (per CTA) ----------------
// A stages: 3 x 16384B (128 rows x 128B = 64 fp16 k, SW128) at 0.
// B stages: 3 x 18432B, n-major fp16, pitch 144B, at 49152.
#define ABUF_SZ  16384
#define BOFF     49152
#define BSTG     18432
#define SMEM_TOT 104448

// ======================================================================
// Kernel 0: convert X to fp16 once
// ======================================================================
__global__ __launch_bounds__(256)
void preconv_kernel(const float* __restrict__ x)
{
    size_t i = (size_t)(blockIdx.x * 256 + threadIdx.x);
    size_t stride = (size_t)gridDim.x * 256;
    const size_t n4 = (size_t)TOK * DIM / 4;
    uint2* dst = (uint2*)g_x;
    const float4* src = (const float4*)x;
    for (; i < n4; i += stride) {
        float4 v = src[i];
        dst[i] = make_uint2(pkh2(v.x, v.y), pkh2(v.z, v.w));
    }
}

// ======================================================================
// Kernel A: h = silu(X@W1) * (X@W3). CTA: 128m x 64n, 256 thr, 2 CTAs/SM.
// Warp grid 2m x 4n; warp tile 64m x 16n per GEMM. grid = 64*2*16 = 2048.
// 3-stage ring; two-phase B staging within each stage.
// ======================================================================
__global__ __launch_bounds__(256, 2)
void moe_up_kernel(const float* __restrict__ w1,
                   const float* __restrict__ w3)
{
    extern __shared__ __align__(1024) char smem[];
    const uint32_t sbase = smem_u32(smem);
    const int tid  = threadIdx.x;
    const int lane = tid & 31;
    const int wid  = tid >> 5;
    const int bid  = blockIdx.x;
    const int e    = bid >> 5;
    const int rem  = bid & 31;
    const int mt   = rem & 1;
    const int nt   = rem >> 1;

    const __half* xb = g_x + (size_t)(e * TPE + mt * 128) * DIM;
    const float* w1b = w1 + (size_t)e * DIM * HID + nt * 64;
    const float* w3b = w3 + (size_t)e * DIM * HID + nt * 64;

    const int wm = wid >> 2, wn = wid & 3;
    const int mbase = wm * 64, nbase = wn * 16;
    const int blk = lane >> 3, r = lane & 7;

    const int am = tid >> 3, aq = tid & 7;    // A rows am + j*32
    const int nb = tid & 63, kq = tid >> 6;   // B: n row, k-oct kq + ph*4

    auto cpA = [&](int s) {
        const uint32_t buf = sbase + (uint32_t)(s % 3) * ABUF_SZ;
        const int k0 = s * 64;
        #pragma unroll
        for (int j = 0; j < 4; j++) {
            int m = am + j * 32;
            cp16(buf + SWZ(m * 128 + aq * 16), xb + (size_t)m * DIM + k0 + aq * 8);
        }
    };
    float v1[8], v3[8];
    auto ldgB = [&](int s, int ph) {
        const int k0 = s * 64 + (kq + ph * 4) * 8;
        #pragma unroll
        for (int t = 0; t < 8; t++) {
            v1[t] = w1b[(size_t)(k0 + t) * HID + nb];
            v3[t] = w3b[(size_t)(k0 + t) * HID + nb];
        }
    };
    auto stsB = [&](int s, int ph) {
        char* buf = smem + BOFF + (size_t)(s % 3) * BSTG;
        const int ch = kq + ph * 4;
        uint4 t1 = { pkh2(v1[0], v1[1]), pkh2(v1[2], v1[3]),
                     pkh2(v1[4], v1[5]), pkh2(v1[6], v1[7]) };
        *(uint4*)(buf + nb * 144 + ch * 16) = t1;
        uint4 t3 = { pkh2(v3[0], v3[1]), pkh2(v3[2], v3[3]),
                     pkh2(v3[4], v3[5]), pkh2(v3[6], v3[7]) };
        *(uint4*)(buf + 9216 + nb * 144 + ch * 16) = t3;
    };

    float acc1[4][2][4], acc3[4][2][4];
    #pragma unroll
    for (int i = 0; i < 4; i++)
        #pragma unroll
        for (int j = 0; j < 2; j++)
            #pragma unroll
            for (int k = 0; k < 4; k++) { acc1[i][j][k] = 0.f; acc3[i][j][k] = 0.f; }

    // prologue: fill B(0), B(1); A(0), A(1)
    ldgB(0, 0); stsB(0, 0); ldgB(0, 1); stsB(0, 1);
    ldgB(1, 0); stsB(1, 0); ldgB(1, 1); stsB(1, 1);
    cpA(0); CP_COMMIT();
    cpA(1); CP_COMMIT();

    const int q = lane >> 3, rr = lane & 7;
    const uint32_t brel = (uint32_t)(nbase + (q & 1) * 8 + rr) * 144 + (uint32_t)(q >> 1) * 16;

    const int NS = DIM / 64;   // 32
    #pragma unroll 1
    for (int s = 0; s < NS; s++) {
        CP_WAIT1();
        __syncthreads();
        const uint32_t aA  = sbase + (uint32_t)(s % 3) * ABUF_SZ;
        const uint32_t aB1 = sbase + BOFF + (uint32_t)(s % 3) * BSTG + brel;
        const uint32_t aB3 = aB1 + 9216;
        const bool pre = (s + 2 < NS);

        if (pre) ldgB(s + 2, 0);
        #pragma unroll
        for (int kk = 0; kk < 2; kk++) {
            uint32_t af[4][4];
            #pragma unroll
            for (int m2 = 0; m2 < 4; m2++)
                ldsm4(af[m2], aA + SWZ((mbase + m2 * 16 + (blk & 1) * 8 + r) * 128 + kk * 32 + (blk >> 1) * 16));
            uint32_t bf1[4], bf3[4];
            ldsm4(bf1, aB1 + kk * 32);
            ldsm4(bf3, aB3 + kk * 32);
            #pragma unroll
            for (int m2 = 0; m2 < 4; m2++)
                #pragma unroll
                for (int p = 0; p < 2; p++) {
                    mma16(acc1[m2][p], af[m2], bf1[p], bf1[p + 2]);
                    mma16(acc3[m2][p], af[m2], bf3[p], bf3[p + 2]);
                }
        }
        if (pre) { stsB(s + 2, 0); ldgB(s + 2, 1); }
        #pragma unroll
        for (int kk = 2; kk < 4; kk++) {
            uint32_t af[4][4];
            #pragma unroll
            for (int m2 = 0; m2 < 4; m2++)
                ldsm4(af[m2], aA + SWZ((mbase + m2 * 16 + (blk & 1) * 8 + r) * 128 + kk * 32 + (blk >> 1) * 16));
            uint32_t bf1[4], bf3[4];
            ldsm4(bf1, aB1 + kk * 32);
            ldsm4(bf3, aB3 + kk * 32);
            #pragma unroll
            for (int m2 = 0; m2 < 4; m2++)
                #pragma unroll
                for (int p = 0; p < 2; p++) {
                    mma16(acc1[m2][p], af[m2], bf1[p], bf1[p + 2]);
                    mma16(acc3[m2][p], af[m2], bf3[p], bf3[p + 2]);
                }
        }
        if (pre) { stsB(s + 2, 1); cpA(s + 2); }
        CP_COMMIT();
    }

    // fused SwiGLU epilogue -> g_h (fp16)
    const int g = lane >> 2, t4 = lane & 3;
    __half* hb = g_h + (size_t)(e * TPE + mt * 128) * HID + nt * 64;
    #pragma unroll
    for (int m2 = 0; m2 < 4; m2++) {
        #pragma unroll
        for (int p = 0; p < 2; p++) {
            int row = mbase + m2 * 16 + g;
            int col = nbase + p * 8 + 2 * t4;
            *(uint32_t*)(hb + (size_t)row * HID + col) =
                pkh2(silu(acc1[m2][p][0]) * acc3[m2][p][0],
                     silu(acc1[m2][p][1]) * acc3[m2][p][1]);
            *(uint32_t*)(hb + (size_t)(row + 8) * HID + col) =
                pkh2(silu(acc1[m2][p][2]) * acc3[m2][p][2],
                     silu(acc1[m2][p][3]) * acc3[m2][p][3]);
        }
    }
}

// ======================================================================
// Kernel B: out = h @ W2. CTA: 128m x 128n, 256 thr, 2 CTAs/SM.
// Warp grid 2m x 4n; warp tile 64m x 32n. grid = 64*2*16 = 2048.
// ======================================================================
__global__ __launch_bounds__(256, 2)
void moe_down_kernel(const float* __restrict__ w2, float* __restrict__ out)
{
    extern __shared__ __align__(1024) char smem[];
    const uint32_t sbase = smem_u32(smem);
    const int tid  = threadIdx.x;
    const int lane = tid & 31;
    const int wid  = tid >> 5;
    const int bid  = blockIdx.x;
    const int e    = bid >> 5;
    const int rem  = bid & 31;
    const int mt   = rem & 1;
    const int nt   = rem >> 1;

    const __half* hb = g_h + (size_t)(e * TPE + mt * 128) * HID;
    const float* w2b = w2 + (size_t)e * HID * DIM + nt * 128;

    const int wm = wid >> 2, wn = wid & 3;
    const int mbase = wm * 64, nbase = wn * 32;
    const int blk = lane >> 3, r = lane & 7;

    const int am = tid >> 3, aq = tid & 7;     // A rows am + j*32
    const int nb = tid & 127, kg = tid >> 7;   // B: n row, octs kg + ph*4 + j*2

    auto cpA = [&](int s) {
        const uint32_t buf = sbase + (uint32_t)(s % 3) * ABUF_SZ;
        const int k0 = s * 64;
        #pragma unroll
        for (int j = 0; j < 4; j++) {
            int m = am + j * 32;
            cp16(buf + SWZ(m * 128 + aq * 16), hb + (size_t)m * HID + k0 + aq * 8);
        }
    };
    float vB[2][8];
    auto ldgB = [&](int s, int ph) {
        #pragma unroll
        for (int j = 0; j < 2; j++) {
            const int k0 = s * 64 + (kg + ph * 4 + j * 2) * 8;
            const float* p = w2b + (size_t)k0 * DIM + nb;
            #pragma unroll
            for (int t = 0; t < 8; t++)
                vB[j][t] = p[(size_t)t * DIM];
        }
    };
    auto stsB = [&](int s, int ph) {
        char* buf = smem + BOFF + (size_t)(s % 3) * BSTG;
        #pragma unroll
        for (int j = 0; j < 2; j++) {
            const int ch = kg + ph * 4 + j * 2;
            uint4 t = { pkh2(vB[j][0], vB[j][1]), pkh2(vB[j][2], vB[j][3]),
                        pkh2(vB[j][4], vB[j][5]), pkh2(vB[j][6], vB[j][7]) };
            *(uint4*)(buf + nb * 144 + ch * 16) = t;
        }
    };

    float acc[4][4][4];
    #pragma unroll
    for (int i = 0; i < 4; i++)
        #pragma unroll
        for (int j = 0; j < 4; j++)
            #pragma unroll
            for (int k = 0; k < 4; k++) acc[i][j][k] = 0.f;

    ldgB(0, 0); stsB(0, 0); ldgB(0, 1); stsB(0, 1);
    ldgB(1, 0); stsB(1, 0); ldgB(1, 1); stsB(1, 1);
    cpA(0); CP_COMMIT();
    cpA(1); CP_COMMIT();

    const int q = lane >> 3, rr = lane & 7;
    const uint32_t brel = (uint32_t)(nbase + (q & 1) * 8 + rr) * 144 + (uint32_t)(q >> 1) * 16;

    const int NS = HID / 64;   // 16
    #pragma unroll 1
    for (int s = 0; s < NS; s++) {
        CP_WAIT1();
        __syncthreads();
        const uint32_t aA = sbase + (uint32_t)(s % 3) * ABUF_SZ;
        const uint32_t aB = sbase + BOFF + (uint32_t)(s % 3) * BSTG + brel;
        const bool pre = (s + 2 < NS);

        if (pre) ldgB(s + 2, 0);
        #pragma unroll
        for (int kk = 0; kk < 2; kk++) {
            uint32_t af[4][4];
            #pragma unroll
            for (int m2 = 0; m2 < 4; m2++)
                ldsm4(af[m2], aA + SWZ((mbase + m2 * 16 + (blk & 1) * 8 + r) * 128 + kk * 32 + (blk >> 1) * 16));
            uint32_t bf[2][4];
            ldsm4(bf[0], aB + kk * 32);
            ldsm4(bf[1], aB + 2304 + kk * 32);
            #pragma unroll
            for (int m2 = 0; m2 < 4; m2++)
                #pragma unroll
                for (int p = 0; p < 4; p++)
                    mma16(acc[m2][p], af[m2], bf[p >> 1][p & 1], bf[p >> 1][(p & 1) + 2]);
        }
        if (pre) { stsB(s + 2, 0); ldgB(s + 2, 1); }
        #pragma unroll
        for (int kk = 2; kk < 4; kk++) {
            uint32_t af[4][4];
            #pragma unroll
            for (int m2 = 0; m2 < 4; m2++)
                ldsm4(af[m2], aA + SWZ((mbase + m2 * 16 + (blk & 1) * 8 + r) * 128 + kk * 32 + (blk >> 1) * 16));
            uint32_t bf[2][4];
            ldsm4(bf[0], aB + kk * 32);
            ldsm4(bf[1], aB + 2304 + kk * 32);
            #pragma unroll
            for (int m2 = 0; m2 < 4; m2++)
                #pragma unroll
                for (int p = 0; p < 4; p++)
                    mma16(acc[m2][p], af[m2], bf[p >> 1][p & 1], bf[p >> 1][(p & 1) + 2]);
        }
        if (pre) { stsB(s + 2, 1); cpA(s + 2); }
        CP_COMMIT();
    }

    const int g = lane >> 2, t4 = lane & 3;
    float* ob = out + (size_t)(e * TPE + mt * 128) * DIM + nt * 128;
    #pragma unroll
    for (int m2 = 0; m2 < 4; m2++) {
        #pragma unroll
        for (int p = 0; p < 4; p++) {
            int row = mbase + m2 * 16 + g;
            int col = nbase + p * 8 + 2 * t4;
            float* r0 = ob + (size_t)row * DIM + col;
            float* r1p = r0 + 8 * DIM;
            *(float2*)r0 = make_float2(acc[m2][p][0], acc[m2][p][1]);
            *(float2*)r1p = make_float2(acc[m2][p][2], acc[m2][p][3]);
        }
    }
}

// ======================================================================
extern "C" void kernel_launch(void* const* d_in, const int* in_sizes, int n_in,
                              void* d_out, int out_size)
{
    (void)in_sizes; (void)n_in; (void)out_size;
    const float* x  = (const float*)d_in[0];
    const float* w1 = (const float*)d_in[1];
    const float* w2 = (const float*)d_in[2];
    const float* w3 = (const float*)d_in[3];
    float* out = (float*)d_out;

    static bool attr_set = false;
    if (!attr_set) {
        cudaFuncSetAttribute(moe_up_kernel,   cudaFuncAttributeMaxDynamicSharedMemorySize, SMEM_TOT);
        cudaFuncSetAttribute(moe_down_kernel, cudaFuncAttributeMaxDynamicSharedMemorySize, SMEM_TOT);
        attr_set = true;
    }

    preconv_kernel<<<2048, 256>>>(x);
    moe_up_kernel<<<NEXP * 32, 256, SMEM_TOT>>>(w1, w3);
    moe_down_kernel<<<NEXP * 32, 256, SMEM_TOT>>>(w2, out);
}

// round 16
// speedup vs baseline: 1.0660x; 1.0660x over previous
#include <cuda_runtime.h>
#include <cuda_fp16.h>
#include <cstdint>

// ---------------- problem constants ----------------
#define NEXP 64
#define DIM  2048
#define HID  1024
#define TOK  16384
#define TPE  256

// scratch: fp16 SwiGLU intermediate + fp16 pre-converted X
__device__ __half g_h[(size_t)TOK * HID];
__device__ __half g_x[(size_t)TOK * DIM];

// ---------------- helpers ----------------
__device__ __forceinline__ uint32_t smem_u32(const void* p) {
    uint32_t a;
    asm("{ .reg .u64 t; cvta.to.shared.u64 t, %1; cvt.u32.u64 %0, t; }" : "=r"(a) : "l"(p));
    return a;
}
__device__ __forceinline__ uint32_t pkh2(float lo, float hi) {
    uint32_t r;
    asm("cvt.rn.f16x2.f32 %0, %1, %2;" : "=r"(r) : "f"(hi), "f"(lo));
    return r;
}

#define SWZ(x) ((x) ^ (((x) >> 3) & 0x70))

__device__ __forceinline__ void cp16(uint32_t dst, const void* src) {
    asm volatile("cp.async.cg.shared.global [%0], [%1], 16;" :: "r"(dst), "l"(src));
}
#define CP_COMMIT() asm volatile("cp.async.commit_group;" ::: "memory")
#define CP_WAIT2()  asm volatile("cp.async.wait_group 2;" ::: "memory")

__device__ __forceinline__ void ldsm4(uint32_t* f, uint32_t addr) {
    asm volatile("ldmatrix.sync.aligned.m8n8.x4.shared.b16 {%0,%1,%2,%3}, [%4];"
                 : "=r"(f[0]), "=r"(f[1]), "=r"(f[2]), "=r"(f[3]) : "r"(addr));
}

__device__ __forceinline__ void mma16(float* d, const uint32_t* a, uint32_t b0, uint32_t b1) {
    asm volatile("mma.sync.aligned.m16n8k16.row.col.f32.f16.f16.f32 "
                 "{%0,%1,%2,%3},{%4,%5,%6,%7},{%8,%9},{%0,%1,%2,%3};"
                 : "+f"(d[0]), "+f"(d[1]), "+f"(d[2]), "+f"(d[3])
                 : "r"(a[0]), "r"(a[1]), "r"(a[2]), "r"(a[3]), "r"(b0), "r"(b1));
}

__device__ __forceinline__ float silu(float v) {
    return v / (1.0f + __expf(-v));
}

// ---------------- smem layout ----------------
// A stages: 4 x 32768B (256 rows x 128B = 64 fp16 k, SW128) at offset 0.
// B stages: n-major fp16, pitch 144B, at 131072. 18432B/stage.
#define ABUF_SZ  32768
#define BOFF     131072
#define BSTG     18432
#define SMEM_TOT 204800

// ======================================================================
// Kernel 0: convert X to fp16 once
// ======================================================================
__global__ __launch_bounds__(256)
void preconv_kernel(const float* __restrict__ x)
{
    size_t i = (size_t)(blockIdx.x * 256 + threadIdx.x);
    size_t stride = (size_t)gridDim.x * 256;
    const size_t n4 = (size_t)TOK * DIM / 4;
    uint2* dst = (uint2*)g_x;
    const float4* src = (const float4*)x;
    for (; i < n4; i += stride) {
        float4 v = src[i];
        dst[i] = make_uint2(pkh2(v.x, v.y), pkh2(v.z, v.w));
    }
}

// ======================================================================
// Kernel A: h = silu(X@W1) * (X@W3). CTA: 256m x 64n (dual B), 512 thr.
// Warp grid 4m x 4n; warp tile 64m x 16n per GEMM. grid = 64*16 = 1024.
// B loaded as float2 pairs along n (LDG.64) -> half the LDG count.
// ======================================================================
__global__ __launch_bounds__(512, 1)
void moe_up_kernel(const float* __restrict__ w1,
                   const float* __restrict__ w3)
{
    extern __shared__ __align__(1024) char smem[];
    const uint32_t sbase = smem_u32(smem);
    const int tid  = threadIdx.x;
    const int lane = tid & 31;
    const int wid  = tid >> 5;
    const int bid  = blockIdx.x;
    const int e    = bid >> 4;
    const int nt   = bid & 15;

    const __half* xb = g_x + (size_t)(e * TPE) * DIM;
    const float* w1b = w1 + (size_t)e * DIM * HID + nt * 64;
    const float* w3b = w3 + (size_t)e * DIM * HID + nt * 64;

    const int wm = wid >> 2, wn = wid & 3;
    const int mbase = wm * 64, nbase = wn * 16;
    const int blk = lane >> 3, r = lane & 7;

    const int am = tid >> 3, aq = tid & 7;       // A rows am + j*64
    // B loader: sel picks W1/W3; each thread owns 2 adjacent n x one k-oct
    const int sel  = tid >> 8;                    // 0 = W1, 1 = W3
    const int nb2  = (tid & 31) * 2;              // n pair base
    const int kq8  = (tid >> 5) & 7;              // k-oct
    const float* wsel = sel ? w3b : w1b;
    const uint32_t bsel = sel ? 9216u : 0u;

    auto cpA = [&](int s) {
        const uint32_t buf = sbase + (uint32_t)(s & 3) * ABUF_SZ;
        const int k0 = s * 64;
        #pragma unroll
        for (int j = 0; j < 4; j++) {
            int m = am + j * 64;
            cp16(buf + SWZ(m * 128 + aq * 16), xb + (size_t)m * DIM + k0 + aq * 8);
        }
    };
    float2 v[8];
    auto ldgB = [&](int s) {
        const int k0 = s * 64 + kq8 * 8;
        const float* p = wsel + (size_t)k0 * HID + nb2;
        #pragma unroll
        for (int t = 0; t < 8; t++)
            v[t] = *(const float2*)(p + (size_t)t * HID);
    };
    auto stsB = [&](int s) {
        char* buf = smem + BOFF + (size_t)(s & 3) * BSTG + bsel;
        uint4 t0 = { pkh2(v[0].x, v[1].x), pkh2(v[2].x, v[3].x),
                     pkh2(v[4].x, v[5].x), pkh2(v[6].x, v[7].x) };
        *(uint4*)(buf + nb2 * 144 + kq8 * 16) = t0;
        uint4 t1 = { pkh2(v[0].y, v[1].y), pkh2(v[2].y, v[3].y),
                     pkh2(v[4].y, v[5].y), pkh2(v[6].y, v[7].y) };
        *(uint4*)(buf + (nb2 + 1) * 144 + kq8 * 16) = t1;
    };

    float acc1[4][2][4], acc3[4][2][4];
    #pragma unroll
    for (int i = 0; i < 4; i++)
        #pragma unroll
        for (int j = 0; j < 2; j++)
            #pragma unroll
            for (int k = 0; k < 4; k++) { acc1[i][j][k] = 0.f; acc3[i][j][k] = 0.f; }

    ldgB(0); stsB(0);
    ldgB(1); stsB(1);
    ldgB(2);
    cpA(0); CP_COMMIT();
    cpA(1); CP_COMMIT();
    cpA(2); CP_COMMIT();

    const int q = lane >> 3, rr = lane & 7;
    const uint32_t brel = (uint32_t)(nbase + (q & 1) * 8 + rr) * 144 + (uint32_t)(q >> 1) * 16;

    const int NS = DIM / 64;   // 32
    #pragma unroll 1
    for (int s = 0; s < NS; s++) {
        CP_WAIT2();
        __syncthreads();
        const uint32_t aA  = sbase + (uint32_t)(s & 3) * ABUF_SZ;
        const uint32_t aB1 = sbase + BOFF + (uint32_t)(s & 3) * BSTG + brel;
        const uint32_t aB3 = aB1 + 9216;
        #pragma unroll
        for (int kk = 0; kk < 4; kk++) {
            uint32_t af[4][4];
            #pragma unroll
            for (int m2 = 0; m2 < 4; m2++)
                ldsm4(af[m2], aA + SWZ((mbase + m2 * 16 + (blk & 1) * 8 + r) * 128 + kk * 32 + (blk >> 1) * 16));
            uint32_t bf1[4], bf3[4];
            ldsm4(bf1, aB1 + kk * 32);
            ldsm4(bf3, aB3 + kk * 32);
            #pragma unroll
            for (int m2 = 0; m2 < 4; m2++)
                #pragma unroll
                for (int p = 0; p < 2; p++) {
                    mma16(acc1[m2][p], af[m2], bf1[p], bf1[p + 2]);
                    mma16(acc3[m2][p], af[m2], bf3[p], bf3[p + 2]);
                }
        }
        if (s + 2 < NS) stsB(s + 2);
        if (s + 3 < NS) { ldgB(s + 3); cpA(s + 3); }
        CP_COMMIT();
    }

    // fused SwiGLU epilogue -> g_h (fp16)
    const int g = lane >> 2, t4 = lane & 3;
    __half* hb = g_h + (size_t)(e * TPE) * HID + nt * 64;
    #pragma unroll
    for (int m2 = 0; m2 < 4; m2++) {
        #pragma unroll
        for (int p = 0; p < 2; p++) {
            int row = mbase + m2 * 16 + g;
            int col = nbase + p * 8 + 2 * t4;
            *(uint32_t*)(hb + (size_t)row * HID + col) =
                pkh2(silu(acc1[m2][p][0]) * acc3[m2][p][0],
                     silu(acc1[m2][p][1]) * acc3[m2][p][1]);
            *(uint32_t*)(hb + (size_t)(row + 8) * HID + col) =
                pkh2(silu(acc1[m2][p][2]) * acc3[m2][p][2],
                     silu(acc1[m2][p][3]) * acc3[m2][p][3]);
        }
    }
}

// ======================================================================
// Kernel B: out = h @ W2. CTA: 256m x 128n, 512 thr.
// Warp grid 4m x 4n; warp tile 64m x 32n. grid = 1024.
// B loaded as float2 pairs along n (LDG.64).
// ======================================================================
__global__ __launch_bounds__(512, 1)
void moe_down_kernel(const float* __restrict__ w2, float* __restrict__ out)
{
    extern __shared__ __align__(1024) char smem[];
    const uint32_t sbase = smem_u32(smem);
    const int tid  = threadIdx.x;
    const int lane = tid & 31;
    const int wid  = tid >> 5;
    const int bid  = blockIdx.x;
    const int e    = bid >> 4;
    const int nt   = bid & 15;

    const __half* hb = g_h + (size_t)(e * TPE) * HID;
    const float* w2b = w2 + (size_t)e * HID * DIM + nt * 128;

    const int wm = wid >> 2, wn = wid & 3;
    const int mbase = wm * 64, nbase = wn * 32;
    const int blk = lane >> 3, r = lane & 7;

    const int am = tid >> 3, aq = tid & 7;       // A rows am + j*64
    const int nb2 = (tid & 63) * 2;               // n pair base (0..126)
    const int kq8 = (tid >> 6) & 7;               // k-oct

    auto cpA = [&](int s) {
        const uint32_t buf = sbase + (uint32_t)(s & 3) * ABUF_SZ;
        const int k0 = s * 64;
        #pragma unroll
        for (int j = 0; j < 4; j++) {
            int m = am + j * 64;
            cp16(buf + SWZ(m * 128 + aq * 16), hb + (size_t)m * HID + k0 + aq * 8);
        }
    };
    float2 v[8];
    auto ldgB = [&](int s) {
        const int k0 = s * 64 + kq8 * 8;
        const float* p = w2b + (size_t)k0 * DIM + nb2;
        #pragma unroll
        for (int t = 0; t < 8; t++)
            v[t] = *(const float2*)(p + (size_t)t * DIM);
    };
    auto stsB = [&](int s) {
        char* buf = smem + BOFF + (size_t)(s & 3) * BSTG;
        uint4 t0 = { pkh2(v[0].x, v[1].x), pkh2(v[2].x, v[3].x),
                     pkh2(v[4].x, v[5].x), pkh2(v[6].x, v[7].x) };
        *(uint4*)(buf + nb2 * 144 + kq8 * 16) = t0;
        uint4 t1 = { pkh2(v[0].y, v[1].y), pkh2(v[2].y, v[3].y),
                     pkh2(v[4].y, v[5].y), pkh2(v[6].y, v[7].y) };
        *(uint4*)(buf + (nb2 + 1) * 144 + kq8 * 16) = t1;
    };

    float acc[4][4][4];
    #pragma unroll
    for (int i = 0; i < 4; i++)
        #pragma unroll
        for (int j = 0; j < 4; j++)
            #pragma unroll
            for (int k = 0; k < 4; k++) acc[i][j][k] = 0.f;

    ldgB(0); stsB(0);
    ldgB(1); stsB(1);
    ldgB(2);
    cpA(0); CP_COMMIT();
    cpA(1); CP_COMMIT();
    cpA(2); CP_COMMIT();

    const int q = lane >> 3, rr = lane & 7;
    const uint32_t brel = (uint32_t)(nbase + (q & 1) * 8 + rr) * 144 + (uint32_t)(q >> 1) * 16;

    const int NS = HID / 64;   // 16
    #pragma unroll 1
    for (int s = 0; s < NS; s++) {
        CP_WAIT2();
        __syncthreads();
        const uint32_t aA = sbase + (uint32_t)(s & 3) * ABUF_SZ;
        const uint32_t aB = sbase + BOFF + (uint32_t)(s & 3) * BSTG + brel;
        #pragma unroll
        for (int kk = 0; kk < 4; kk++) {
            uint32_t af[4][4];
            #pragma unroll
            for (int m2 = 0; m2 < 4; m2++)
                ldsm4(af[m2], aA + SWZ((mbase + m2 * 16 + (blk & 1) * 8 + r) * 128 + kk * 32 + (blk >> 1) * 16));
            uint32_t bf[2][4];
            ldsm4(bf[0], aB + kk * 32);
            ldsm4(bf[1], aB + 2304 + kk * 32);
            #pragma unroll
            for (int m2 = 0; m2 < 4; m2++)
                #pragma unroll
                for (int p = 0; p < 4; p++)
                    mma16(acc[m2][p], af[m2], bf[p >> 1][p & 1], bf[p >> 1][(p & 1) + 2]);
        }
        if (s + 2 < NS) stsB(s + 2);
        if (s + 3 < NS) { ldgB(s + 3); cpA(s + 3); }
        CP_COMMIT();
    }

    const int g = lane >> 2, t4 = lane & 3;
    float* ob = out + (size_t)(e * TPE) * DIM + nt * 128;
    #pragma unroll
    for (int m2 = 0; m2 < 4; m2++) {
        #pragma unroll
        for (int p = 0; p < 4; p++) {
            int row = mbase + m2 * 16 + g;
            int col = nbase + p * 8 + 2 * t4;
            float* r0 = ob + (size_t)row * DIM + col;
            float* r1p = r0 + 8 * DIM;
            *(float2*)r0 = make_float2(acc[m2][p][0], acc[m2][p][1]);
            *(float2*)r1p = make_float2(acc[m2][p][2], acc[m2][p][3]);
        }
    }
}

// ======================================================================
extern "C" void kernel_launch(void* const* d_in, const int* in_sizes, int n_in,
                              void* d_out, int out_size)
{
    (void)in_sizes; (void)n_in; (void)out_size;
    const float* x  = (const float*)d_in[0];
    const float* w1 = (const float*)d_in[1];
    const float* w2 = (const float*)d_in[2];
    const float* w3 = (const float*)d_in[3];
    float* out = (float*)d_out;

    static bool attr_set = false;
    if (!attr_set) {
        cudaFuncSetAttribute(moe_up_kernel,   cudaFuncAttributeMaxDynamicSharedMemorySize, SMEM_TOT);
        cudaFuncSetAttribute(moe_down_kernel, cudaFuncAttributeMaxDynamicSharedMemorySize, SMEM_TOT);
        attr_set = true;
    }

    preconv_kernel<<<2048, 256>>>(x);
    moe_up_kernel<<<NEXP * 16, 512, SMEM_TOT>>>(w1, w3);
    moe_down_kernel<<<NEXP * 16, 512, SMEM_TOT>>>(w2, out);
}